// round 6
// baseline (speedup 1.0000x reference)
#include <cuda_runtime.h>
#include <cstdint>

#define SEQ 8192
#define DIM 64
#define WIN 64
#define QPB 64
#define NTHREADS 256
#define ROWS 192            // staged key rows: QPB + 2*WIN
#define ROWB 144            // smem row stride bytes: 64 halfs + 8 pad halfs

#define KH_OFF 0
#define KL_OFF (KH_OFF + ROWS*ROWB)
#define VH_OFF (KL_OFF + ROWS*ROWB)
#define VL_OFF (VH_OFF + ROWS*ROWB)
#define SMEM_BYTES (VL_OFF + ROWS*ROWB)   // 110592
#define CBS 68              // combine-buffer row stride in floats (272B)

__device__ __forceinline__ uint32_t smem_u32(const void* p) {
    uint32_t a; asm("{ .reg .u64 t; cvta.to.shared.u64 t, %1; cvt.u32.u64 %0, t; }" : "=r"(a) : "l"(p));
    return a;
}
__device__ __forceinline__ float ex2f(float x) { float r; asm("ex2.approx.f32 %0,%1;" : "=f"(r) : "f"(x)); return r; }
__device__ __forceinline__ uint32_t pack_bf16x2(float hi, float lo) {
    uint32_t r; asm("cvt.rn.bf16x2.f32 %0,%1,%2;" : "=r"(r) : "f"(hi), "f"(lo)); return r;
}
// split (a,b) fp32 pair into bf16 hi pair {lo:a,hi:b} (truncation) + bf16 lo (residual) pair
__device__ __forceinline__ void split2(float a, float b, uint32_t& h, uint32_t& l) {
    uint32_t ba = __float_as_uint(a) & 0xFFFF0000u;
    uint32_t bb = __float_as_uint(b) & 0xFFFF0000u;
    h = __byte_perm(ba, bb, 0x7632);
    l = pack_bf16x2(b - __uint_as_float(bb), a - __uint_as_float(ba));
}

__device__ __forceinline__ void ldsm4(uint32_t r[4], uint32_t addr) {
    asm volatile("ldmatrix.sync.aligned.m8n8.x4.shared.b16 {%0,%1,%2,%3}, [%4];"
        : "=r"(r[0]), "=r"(r[1]), "=r"(r[2]), "=r"(r[3]) : "r"(addr));
}
__device__ __forceinline__ void ldsm4t(uint32_t r[4], uint32_t addr) {
    asm volatile("ldmatrix.sync.aligned.m8n8.x4.trans.shared.b16 {%0,%1,%2,%3}, [%4];"
        : "=r"(r[0]), "=r"(r[1]), "=r"(r[2]), "=r"(r[3]) : "r"(addr));
}
__device__ __forceinline__ void mma_bf16(float c[4], const uint32_t a[4], uint32_t b0, uint32_t b1) {
    asm volatile("mma.sync.aligned.m16n8k16.row.col.f32.bf16.bf16.f32 "
        "{%0,%1,%2,%3}, {%4,%5,%6,%7}, {%8,%9}, {%0,%1,%2,%3};"
        : "+f"(c[0]), "+f"(c[1]), "+f"(c[2]), "+f"(c[3])
        : "r"(a[0]), "r"(a[1]), "r"(a[2]), "r"(a[3]), "r"(b0), "r"(b1));
}

__global__ void __launch_bounds__(NTHREADS, 2)
swa_hmma_kernel(const float* __restrict__ q, const float* __restrict__ k,
                const float* __restrict__ v, float* __restrict__ out)
{
    extern __shared__ char smem[];
    const uint32_t sb = smem_u32(smem);
    const int t = threadIdx.x;

    const int tilesPerB = SEQ / QPB;
    const int b  = blockIdx.x / tilesPerB;
    const int Q0 = (blockIdx.x % tilesPerB) * QPB;

    const float* qb = q + (size_t)b * SEQ * DIM;
    const float* kb = k + (size_t)b * SEQ * DIM;
    const float* vb = v + (size_t)b * SEQ * DIM;
    float*       ob = out + (size_t)b * SEQ * DIM;

    // ---- stage K and V rows [Q0-64, Q0+128), zero-filled out of range ----
    for (int idx = t; idx < ROWS * 16; idx += NTHREADS) {
        int r = idx >> 4, c4 = idx & 15;
        int j = Q0 - WIN + r;
        float4 kk = make_float4(0.f, 0.f, 0.f, 0.f);
        float4 vv = make_float4(0.f, 0.f, 0.f, 0.f);
        if (j >= 0 && j < SEQ) {
            kk = ((const float4*)(kb + (size_t)j * DIM))[c4];
            vv = ((const float4*)(vb + (size_t)j * DIM))[c4];
        }
        uint32_t h01, l01, h23, l23;
        split2(kk.x, kk.y, h01, l01); split2(kk.z, kk.w, h23, l23);
        *(uint2*)(smem + KH_OFF + r * ROWB + c4 * 8) = make_uint2(h01, h23);
        *(uint2*)(smem + KL_OFF + r * ROWB + c4 * 8) = make_uint2(l01, l23);
        split2(vv.x, vv.y, h01, l01); split2(vv.z, vv.w, h23, l23);
        *(uint2*)(smem + VH_OFF + r * ROWB + c4 * 8) = make_uint2(h01, h23);
        *(uint2*)(smem + VL_OFF + r * ROWB + c4 * 8) = make_uint2(l01, l23);
    }

    const int w    = t >> 5;
    const int l    = t & 31;
    const int pair = w & 3;        // query group: rows Q0+pair*16 .. +15
    const int h    = w >> 2;       // key-span half: 0 -> lk [0,80), 1 -> lk [80,144)
    const int NT    = h ? 8  : 10; // S n-tiles this warp
    const int NKS   = h ? 4  : 5;  // PV k-steps this warp
    const int lkoff = h ? 80 : 0;

    // ---- build Q A-fragments straight from gmem (prescale + hi/lo split) ----
    // m16n8k16 A mapping: a0=(g, c2), a1=(g+8, c2), a2=(g, c2+8), a3=(g+8, c2+8)
    const float PRE = 0.125f * 1.4426950408889634f;   // 1/sqrt(D) * log2(e)
    uint32_t aqh[4][4], aql[4][4];
    {
        const int g  = l >> 2;
        const int c2 = (l & 3) * 2;
        const float* q0 = qb + (size_t)(Q0 + pair * 16 + g) * DIM + c2;
        const float* q1 = q0 + 8 * DIM;
        #pragma unroll
        for (int ks = 0; ks < 4; ks++) {
            #pragma unroll
            for (int half = 0; half < 2; half++) {
                float2 f0 = *(const float2*)(q0 + ks * 16 + half * 8);
                float2 f1 = *(const float2*)(q1 + ks * 16 + half * 8);
                split2(f0.x * PRE, f0.y * PRE, aqh[ks][half * 2],     aql[ks][half * 2]);
                split2(f1.x * PRE, f1.y * PRE, aqh[ks][half * 2 + 1], aql[ks][half * 2 + 1]);
            }
        }
    }
    __syncthreads();

    // ---- S = Q K^T over this half's key span ----
    float sacc[10][4];
    #pragma unroll
    for (int nt = 0; nt < 10; nt++)
        #pragma unroll
        for (int i = 0; i < 4; i++) sacc[nt][i] = 0.f;

    {
        // x4 lane addressing: lanes 0-15 -> KH col-chunks, lanes 16-31 -> KL
        uint32_t kaddr = sb + KH_OFF
                       + (uint32_t)(pair * 16 + lkoff + (l & 7)) * ROWB
                       + ((l >> 3) & 1) * 16
                       + (l >> 4) * (KL_OFF - KH_OFF);
        #pragma unroll
        for (int nt = 0; nt < 10; nt++) {
            if (nt >= NT) break;
            #pragma unroll
            for (int ks = 0; ks < 4; ks++) {
                uint32_t bb[4];
                ldsm4(bb, kaddr + (uint32_t)nt * 8 * ROWB + ks * 32);
                mma_bf16(sacc[nt], aqh[ks], bb[0], bb[1]);
                mma_bf16(sacc[nt], aqh[ks], bb[2], bb[3]);
                mma_bf16(sacc[nt], aql[ks], bb[0], bb[1]);
            }
        }
    }

    // ---- masked exp + partial row sums (scores already in log2 domain) ----
    const int jbase = Q0 - WIN + pair * 16;
    const int m0 = l >> 2;
    const int cc = (l & 3) * 2;
    float rs0 = 0.f, rs1 = 0.f;
    #pragma unroll
    for (int nt = 0; nt < 10; nt++) {
        if (nt >= NT) break;
        int lk = lkoff + nt * 8 + cc;
        bool ok0a = ((unsigned)(lk     - m0) <= 2u * WIN) && ((unsigned)(jbase + lk)     < SEQ);
        bool ok0b = ((unsigned)(lk + 1 - m0) <= 2u * WIN) && ((unsigned)(jbase + lk + 1) < SEQ);
        bool ok1a = ((unsigned)(lk     - m0 - 8) <= 2u * WIN) && ((unsigned)(jbase + lk)     < SEQ);
        bool ok1b = ((unsigned)(lk + 1 - m0 - 8) <= 2u * WIN) && ((unsigned)(jbase + lk + 1) < SEQ);
        float p0 = ok0a ? ex2f(sacc[nt][0]) : 0.f;
        float p1 = ok0b ? ex2f(sacc[nt][1]) : 0.f;
        float p2 = ok1a ? ex2f(sacc[nt][2]) : 0.f;
        float p3 = ok1b ? ex2f(sacc[nt][3]) : 0.f;
        sacc[nt][0] = p0; sacc[nt][1] = p1; sacc[nt][2] = p2; sacc[nt][3] = p3;
        rs0 += p0 + p1;
        rs1 += p2 + p3;
    }
    rs0 += __shfl_xor_sync(0xFFFFFFFFu, rs0, 1);
    rs0 += __shfl_xor_sync(0xFFFFFFFFu, rs0, 2);
    rs1 += __shfl_xor_sync(0xFFFFFFFFu, rs1, 1);
    rs1 += __shfl_xor_sync(0xFFFFFFFFu, rs1, 2);

    // ---- O_partial = P_partial V_partial ----
    float oacc[8][4];
    #pragma unroll
    for (int nt = 0; nt < 8; nt++)
        #pragma unroll
        for (int i = 0; i < 4; i++) oacc[nt][i] = 0.f;

    {
        // x4 trans lanes: 0-15 -> VH (16 rows), 16-31 -> VL
        uint32_t vaddr = sb + VH_OFF
                       + (uint32_t)(pair * 16 + lkoff + (l & 7) + ((l >> 3) & 1) * 8) * ROWB
                       + (l >> 4) * (VL_OFF - VH_OFF);
        #pragma unroll
        for (int ks = 0; ks < 5; ks++) {
            if (ks >= NKS) break;
            uint32_t ah[4], al[4];
            split2(sacc[2*ks][0],   sacc[2*ks][1],   ah[0], al[0]);
            split2(sacc[2*ks][2],   sacc[2*ks][3],   ah[1], al[1]);
            split2(sacc[2*ks+1][0], sacc[2*ks+1][1], ah[2], al[2]);
            split2(sacc[2*ks+1][2], sacc[2*ks+1][3], ah[3], al[3]);
            #pragma unroll
            for (int nt = 0; nt < 8; nt++) {
                uint32_t bb[4];
                ldsm4t(bb, vaddr + (uint32_t)ks * 16 * ROWB + nt * 16);
                mma_bf16(oacc[nt], ah, bb[0], bb[1]);
                mma_bf16(oacc[nt], ah, bb[2], bb[3]);
                mma_bf16(oacc[nt], al, bb[0], bb[1]);
            }
        }
    }

    // ---- combine halves via smem (reuse KH region, dead after S phase) ----
    float* cb = (float*)(smem + KH_OFF);
    __syncthreads();                               // all K/V tile reads done
    if (h == 1) {
        float* p0 = cb + (size_t)(pair * 16 + m0) * CBS;
        float* p1 = p0 + 8 * CBS;
        #pragma unroll
        for (int nt = 0; nt < 8; nt++) {
            *(float2*)(p0 + nt * 8 + cc) = make_float2(oacc[nt][0], oacc[nt][1]);
            *(float2*)(p1 + nt * 8 + cc) = make_float2(oacc[nt][2], oacc[nt][3]);
        }
        if (cc == 0) { p0[64] = rs0; p1[64] = rs1; }
    }
    __syncthreads();
    if (h == 0) {
        const float* p0 = cb + (size_t)(pair * 16 + m0) * CBS;
        const float* p1 = p0 + 8 * CBS;
        #pragma unroll
        for (int nt = 0; nt < 8; nt++) {
            float2 u0 = *(const float2*)(p0 + nt * 8 + cc);
            float2 u1 = *(const float2*)(p1 + nt * 8 + cc);
            oacc[nt][0] += u0.x; oacc[nt][1] += u0.y;
            oacc[nt][2] += u1.x; oacc[nt][3] += u1.y;
        }
        float inv0 = 1.f / (rs0 + p0[64]);
        float inv1 = 1.f / (rs1 + p1[64]);
        float* orow0 = ob + (size_t)(Q0 + pair * 16 + m0) * DIM;
        float* orow1 = orow0 + 8 * DIM;
        #pragma unroll
        for (int nt = 0; nt < 8; nt++) {
            *(float2*)(orow0 + nt * 8 + cc) = make_float2(oacc[nt][0] * inv0, oacc[nt][1] * inv0);
            *(float2*)(orow1 + nt * 8 + cc) = make_float2(oacc[nt][2] * inv1, oacc[nt][3] * inv1);
        }
    }
}

extern "C" void kernel_launch(void* const* d_in, const int* in_sizes, int n_in,
                              void* d_out, int out_size)
{
    const float* q = (const float*)d_in[0];
    const float* k = (const float*)d_in[1];
    const float* v = (const float*)d_in[2];
    float* out = (float*)d_out;

    int B = in_sizes[0] / (SEQ * DIM);

    cudaFuncSetAttribute(swa_hmma_kernel,
                         cudaFuncAttributeMaxDynamicSharedMemorySize, SMEM_BYTES);

    dim3 grid(B * (SEQ / QPB));
    swa_hmma_kernel<<<grid, NTHREADS, SMEM_BYTES>>>(q, k, v, out);
}

// round 8
// speedup vs baseline: 1.0151x; 1.0151x over previous
#include <cuda_runtime.h>
#include <cstdint>

#define SEQ 8192
#define DIM 64
#define WIN 64
#define QPB 128
#define NTHREADS 512
#define ROWS 256            // staged key rows: QPB + 2*WIN
#define ROWB 144            // smem row stride bytes: 64 halfs + 8 pad halfs

#define KH_OFF 0
#define KL_OFF (KH_OFF + ROWS*ROWB)
#define VH_OFF (KL_OFF + ROWS*ROWB)
#define VL_OFF (VH_OFF + ROWS*ROWB)
#define SMEM_BYTES (VL_OFF + ROWS*ROWB)   // 147456
#define CBS 68              // combine-buffer row stride in floats (272B)

__device__ __forceinline__ uint32_t smem_u32(const void* p) {
    uint32_t a; asm("{ .reg .u64 t; cvta.to.shared.u64 t, %1; cvt.u32.u64 %0, t; }" : "=r"(a) : "l"(p));
    return a;
}
__device__ __forceinline__ float ex2f(float x) { float r; asm("ex2.approx.f32 %0,%1;" : "=f"(r) : "f"(x)); return r; }
__device__ __forceinline__ uint32_t pack_bf16x2(float hi, float lo) {
    uint32_t r; asm("cvt.rn.bf16x2.f32 %0,%1,%2;" : "=r"(r) : "f"(hi), "f"(lo)); return r;
}
// split (a,b) fp32 pair into bf16 hi pair {lo:a,hi:b} (truncation) + bf16 lo (residual) pair
__device__ __forceinline__ void split2(float a, float b, uint32_t& h, uint32_t& l) {
    uint32_t ba = __float_as_uint(a) & 0xFFFF0000u;
    uint32_t bb = __float_as_uint(b) & 0xFFFF0000u;
    h = __byte_perm(ba, bb, 0x7632);
    l = pack_bf16x2(b - __uint_as_float(bb), a - __uint_as_float(ba));
}

__device__ __forceinline__ void ldsm4(uint32_t r[4], uint32_t addr) {
    asm volatile("ldmatrix.sync.aligned.m8n8.x4.shared.b16 {%0,%1,%2,%3}, [%4];"
        : "=r"(r[0]), "=r"(r[1]), "=r"(r[2]), "=r"(r[3]) : "r"(addr));
}
__device__ __forceinline__ void ldsm4t(uint32_t r[4], uint32_t addr) {
    asm volatile("ldmatrix.sync.aligned.m8n8.x4.trans.shared.b16 {%0,%1,%2,%3}, [%4];"
        : "=r"(r[0]), "=r"(r[1]), "=r"(r[2]), "=r"(r[3]) : "r"(addr));
}
__device__ __forceinline__ void mma_bf16(float c[4], const uint32_t a[4], uint32_t b0, uint32_t b1) {
    asm volatile("mma.sync.aligned.m16n8k16.row.col.f32.bf16.bf16.f32 "
        "{%0,%1,%2,%3}, {%4,%5,%6,%7}, {%8,%9}, {%0,%1,%2,%3};"
        : "+f"(c[0]), "+f"(c[1]), "+f"(c[2]), "+f"(c[3])
        : "r"(a[0]), "r"(a[1]), "r"(a[2]), "r"(a[3]), "r"(b0), "r"(b1));
}

// S = Q K^T  (fully unrolled, ks-outer/nt-inner for accumulator ILP)
template<int NT>
__device__ __forceinline__ void s_phase(float (*sacc)[4], const uint32_t (*aqh)[4],
                                        const uint32_t (*aql)[4], uint32_t kaddr)
{
    #pragma unroll
    for (int ks = 0; ks < 4; ks++) {
        #pragma unroll
        for (int nt = 0; nt < NT; nt++) {
            uint32_t bb[4];
            ldsm4(bb, kaddr + (uint32_t)nt * 8 * ROWB + ks * 32);
            mma_bf16(sacc[nt], aqh[ks], bb[0], bb[1]);
            mma_bf16(sacc[nt], aqh[ks], bb[2], bb[3]);
            mma_bf16(sacc[nt], aql[ks], bb[0], bb[1]);
        }
    }
}

// masked exp + partial row sums
template<int NT>
__device__ __forceinline__ void exp_phase(float (*sacc)[4], int lkoff, int jbase,
                                          int m0, int cc, float& rs0, float& rs1)
{
    #pragma unroll
    for (int nt = 0; nt < NT; nt++) {
        int lk = lkoff + nt * 8 + cc;
        bool ok0a = ((unsigned)(lk     - m0) <= 2u * WIN) && ((unsigned)(jbase + lk)     < SEQ);
        bool ok0b = ((unsigned)(lk + 1 - m0) <= 2u * WIN) && ((unsigned)(jbase + lk + 1) < SEQ);
        bool ok1a = ((unsigned)(lk     - m0 - 8) <= 2u * WIN) && ((unsigned)(jbase + lk)     < SEQ);
        bool ok1b = ((unsigned)(lk + 1 - m0 - 8) <= 2u * WIN) && ((unsigned)(jbase + lk + 1) < SEQ);
        float p0 = ok0a ? ex2f(sacc[nt][0]) : 0.f;
        float p1 = ok0b ? ex2f(sacc[nt][1]) : 0.f;
        float p2 = ok1a ? ex2f(sacc[nt][2]) : 0.f;
        float p3 = ok1b ? ex2f(sacc[nt][3]) : 0.f;
        sacc[nt][0] = p0; sacc[nt][1] = p1; sacc[nt][2] = p2; sacc[nt][3] = p3;
        rs0 += p0 + p1;
        rs1 += p2 + p3;
    }
}

// O = P V  (fully unrolled; nt-inner gives independent oacc chains)
template<int NKS>
__device__ __forceinline__ void pv_phase(float (*oacc)[4], const float (*sacc)[4], uint32_t vaddr)
{
    #pragma unroll
    for (int ks = 0; ks < NKS; ks++) {
        uint32_t ah[4], al[4];
        split2(sacc[2*ks][0],   sacc[2*ks][1],   ah[0], al[0]);
        split2(sacc[2*ks][2],   sacc[2*ks][3],   ah[1], al[1]);
        split2(sacc[2*ks+1][0], sacc[2*ks+1][1], ah[2], al[2]);
        split2(sacc[2*ks+1][2], sacc[2*ks+1][3], ah[3], al[3]);
        #pragma unroll
        for (int nt = 0; nt < 8; nt++) {
            uint32_t bb[4];
            ldsm4t(bb, vaddr + (uint32_t)ks * 16 * ROWB + nt * 16);
            mma_bf16(oacc[nt], ah, bb[0], bb[1]);
            mma_bf16(oacc[nt], ah, bb[2], bb[3]);
            mma_bf16(oacc[nt], al, bb[0], bb[1]);
        }
    }
}

__global__ void __launch_bounds__(NTHREADS, 1)
swa_hmma_kernel(const float* __restrict__ q, const float* __restrict__ k,
                const float* __restrict__ v, float* __restrict__ out)
{
    extern __shared__ char smem[];
    const uint32_t sb = smem_u32(smem);
    const int t = threadIdx.x;

    const int tilesPerB = SEQ / QPB;
    const int b  = blockIdx.x / tilesPerB;
    const int Q0 = (blockIdx.x % tilesPerB) * QPB;

    const float* qb = q + (size_t)b * SEQ * DIM;
    const float* kb = k + (size_t)b * SEQ * DIM;
    const float* vb = v + (size_t)b * SEQ * DIM;
    float*       ob = out + (size_t)b * SEQ * DIM;

    // ---- stage K and V rows [Q0-64, Q0+192), zero-filled out of range ----
    for (int idx = t; idx < ROWS * 16; idx += NTHREADS) {
        int r = idx >> 4, c4 = idx & 15;
        int j = Q0 - WIN + r;
        float4 kk = make_float4(0.f, 0.f, 0.f, 0.f);
        float4 vv = make_float4(0.f, 0.f, 0.f, 0.f);
        if (j >= 0 && j < SEQ) {
            kk = ((const float4*)(kb + (size_t)j * DIM))[c4];
            vv = ((const float4*)(vb + (size_t)j * DIM))[c4];
        }
        uint32_t h01, l01, h23, l23;
        split2(kk.x, kk.y, h01, l01); split2(kk.z, kk.w, h23, l23);
        *(uint2*)(smem + KH_OFF + r * ROWB + c4 * 8) = make_uint2(h01, h23);
        *(uint2*)(smem + KL_OFF + r * ROWB + c4 * 8) = make_uint2(l01, l23);
        split2(vv.x, vv.y, h01, l01); split2(vv.z, vv.w, h23, l23);
        *(uint2*)(smem + VH_OFF + r * ROWB + c4 * 8) = make_uint2(h01, h23);
        *(uint2*)(smem + VL_OFF + r * ROWB + c4 * 8) = make_uint2(l01, l23);
    }

    const int w    = t >> 5;
    const int l    = t & 31;
    const int pair = w & 7;        // query group: rows Q0+pair*16 .. +15
    const int h    = w >> 3;       // key-span half: 0 -> lk [0,80), 1 -> lk [80,144)
    const int lkoff = h ? 80 : 0;

    // ---- build Q A-fragments straight from gmem (prescale + hi/lo split) ----
    // m16n8k16 A mapping: a0=(g, c2), a1=(g+8, c2), a2=(g, c2+8), a3=(g+8, c2+8)
    const float PRE = 0.125f * 1.4426950408889634f;   // 1/sqrt(D) * log2(e)
    uint32_t aqh[4][4], aql[4][4];
    {
        const int g  = l >> 2;
        const int c2 = (l & 3) * 2;
        const float* q0 = qb + (size_t)(Q0 + pair * 16 + g) * DIM + c2;
        const float* q1 = q0 + 8 * DIM;
        #pragma unroll
        for (int ks = 0; ks < 4; ks++) {
            #pragma unroll
            for (int half = 0; half < 2; half++) {
                float2 f0 = *(const float2*)(q0 + ks * 16 + half * 8);
                float2 f1 = *(const float2*)(q1 + ks * 16 + half * 8);
                split2(f0.x * PRE, f0.y * PRE, aqh[ks][half * 2],     aql[ks][half * 2]);
                split2(f1.x * PRE, f1.y * PRE, aqh[ks][half * 2 + 1], aql[ks][half * 2 + 1]);
            }
        }
    }
    __syncthreads();

    // x4 lane addressing: lanes 0-15 -> KH col-chunks, lanes 16-31 -> KL
    const uint32_t kaddr = sb + KH_OFF
                         + (uint32_t)(pair * 16 + lkoff + (l & 7)) * ROWB
                         + ((l >> 3) & 1) * 16
                         + (l >> 4) * (KL_OFF - KH_OFF);
    // x4 trans lanes: 0-15 -> VH (16 rows), 16-31 -> VL
    const uint32_t vaddr = sb + VH_OFF
                         + (uint32_t)(pair * 16 + lkoff + (l & 7) + ((l >> 3) & 1) * 8) * ROWB
                         + (l >> 4) * (VL_OFF - VH_OFF);

    const int jbase = Q0 - WIN + pair * 16;
    const int m0 = l >> 2;
    const int cc = (l & 3) * 2;
    float rs0 = 0.f, rs1 = 0.f;

    float sacc[10][4];
    #pragma unroll
    for (int nt = 0; nt < 10; nt++)
        #pragma unroll
        for (int i = 0; i < 4; i++) sacc[nt][i] = 0.f;
    float oacc[8][4];
    #pragma unroll
    for (int nt = 0; nt < 8; nt++)
        #pragma unroll
        for (int i = 0; i < 4; i++) oacc[nt][i] = 0.f;

    if (h == 0) {
        s_phase<10>(sacc, aqh, aql, kaddr);
        exp_phase<10>(sacc, 0, jbase, m0, cc, rs0, rs1);
        pv_phase<5>(oacc, sacc, vaddr);
    } else {
        s_phase<8>(sacc, aqh, aql, kaddr);
        exp_phase<8>(sacc, 80, jbase, m0, cc, rs0, rs1);
        pv_phase<4>(oacc, sacc, vaddr);
    }

    rs0 += __shfl_xor_sync(0xFFFFFFFFu, rs0, 1);
    rs0 += __shfl_xor_sync(0xFFFFFFFFu, rs0, 2);
    rs1 += __shfl_xor_sync(0xFFFFFFFFu, rs1, 1);
    rs1 += __shfl_xor_sync(0xFFFFFFFFu, rs1, 2);

    // ---- combine halves via smem (reuse KH region, dead after S phase) ----
    float* cb = (float*)(smem + KH_OFF);
    __syncthreads();                               // all K/V tile reads done
    if (h == 1) {
        float* p0 = cb + (size_t)(pair * 16 + m0) * CBS;
        float* p1 = p0 + 8 * CBS;
        #pragma unroll
        for (int nt = 0; nt < 8; nt++) {
            *(float2*)(p0 + nt * 8 + cc) = make_float2(oacc[nt][0], oacc[nt][1]);
            *(float2*)(p1 + nt * 8 + cc) = make_float2(oacc[nt][2], oacc[nt][3]);
        }
        if (cc == 0) { p0[64] = rs0; p1[64] = rs1; }
    }
    __syncthreads();
    if (h == 0) {
        const float* p0 = cb + (size_t)(pair * 16 + m0) * CBS;
        const float* p1 = p0 + 8 * CBS;
        #pragma unroll
        for (int nt = 0; nt < 8; nt++) {
            float2 u0 = *(const float2*)(p0 + nt * 8 + cc);
            float2 u1 = *(const float2*)(p1 + nt * 8 + cc);
            oacc[nt][0] += u0.x; oacc[nt][1] += u0.y;
            oacc[nt][2] += u1.x; oacc[nt][3] += u1.y;
        }
        float inv0 = 1.f / (rs0 + p0[64]);
        float inv1 = 1.f / (rs1 + p1[64]);
        float* orow0 = ob + (size_t)(Q0 + pair * 16 + m0) * DIM;
        float* orow1 = orow0 + 8 * DIM;
        #pragma unroll
        for (int nt = 0; nt < 8; nt++) {
            *(float2*)(orow0 + nt * 8 + cc) = make_float2(oacc[nt][0] * inv0, oacc[nt][1] * inv0);
            *(float2*)(orow1 + nt * 8 + cc) = make_float2(oacc[nt][2] * inv1, oacc[nt][3] * inv1);
        }
    }
}

extern "C" void kernel_launch(void* const* d_in, const int* in_sizes, int n_in,
                              void* d_out, int out_size)
{
    const float* q = (const float*)d_in[0];
    const float* k = (const float*)d_in[1];
    const float* v = (const float*)d_in[2];
    float* out = (float*)d_out;

    int B = in_sizes[0] / (SEQ * DIM);

    cudaFuncSetAttribute(swa_hmma_kernel,
                         cudaFuncAttributeMaxDynamicSharedMemorySize, SMEM_BYTES);

    dim3 grid(B * (SEQ / QPB));
    swa_hmma_kernel<<<grid, NTHREADS, SMEM_BYTES>>>(q, k, v, out);
}

// round 11
// speedup vs baseline: 1.1775x; 1.1600x over previous
#include <cuda_runtime.h>
#include <cstdint>

#define SEQ 8192
#define DIM 64
#define WIN 64
#define QPB 128
#define NTHREADS 512
#define ROWS 256            // staged key rows: QPB + 2*WIN
#define ROWB 144            // smem row stride bytes: 64 halfs + 8 pad halfs

#define KH_OFF 0
#define KL_OFF (KH_OFF + ROWS*ROWB)
#define VH_OFF (KL_OFF + ROWS*ROWB)
#define VL_OFF (VH_OFF + ROWS*ROWB)
#define SMEM_BYTES (VL_OFF + ROWS*ROWB)   // 147456
#define CBS 68              // combine-buffer row stride in floats (272B)

__device__ __forceinline__ uint32_t smem_u32(const void* p) {
    uint32_t a; asm("{ .reg .u64 t; cvta.to.shared.u64 t, %1; cvt.u32.u64 %0, t; }" : "=r"(a) : "l"(p));
    return a;
}
__device__ __forceinline__ float ex2f(float x) { float r; asm("ex2.approx.f32 %0,%1;" : "=f"(r) : "f"(x)); return r; }
__device__ __forceinline__ uint32_t pack_bf16x2(float hi, float lo) {
    uint32_t r; asm("cvt.rn.bf16x2.f32 %0,%1,%2;" : "=r"(r) : "f"(hi), "f"(lo)); return r;
}
// split (a,b) fp32 pair into bf16 hi pair {lo:a,hi:b} (truncation) + bf16 lo (residual) pair
__device__ __forceinline__ void split2(float a, float b, uint32_t& h, uint32_t& l) {
    uint32_t ba = __float_as_uint(a) & 0xFFFF0000u;
    uint32_t bb = __float_as_uint(b) & 0xFFFF0000u;
    h = __byte_perm(ba, bb, 0x7632);
    l = pack_bf16x2(b - __uint_as_float(bb), a - __uint_as_float(ba));
}

__device__ __forceinline__ void ldsm4(uint32_t r[4], uint32_t addr) {
    asm volatile("ldmatrix.sync.aligned.m8n8.x4.shared.b16 {%0,%1,%2,%3}, [%4];"
        : "=r"(r[0]), "=r"(r[1]), "=r"(r[2]), "=r"(r[3]) : "r"(addr));
}
__device__ __forceinline__ void ldsm4t(uint32_t r[4], uint32_t addr) {
    asm volatile("ldmatrix.sync.aligned.m8n8.x4.trans.shared.b16 {%0,%1,%2,%3}, [%4];"
        : "=r"(r[0]), "=r"(r[1]), "=r"(r[2]), "=r"(r[3]) : "r"(addr));
}
__device__ __forceinline__ void mma_bf16(float c[4], const uint32_t a[4], uint32_t b0, uint32_t b1) {
    asm volatile("mma.sync.aligned.m16n8k16.row.col.f32.bf16.bf16.f32 "
        "{%0,%1,%2,%3}, {%4,%5,%6,%7}, {%8,%9}, {%0,%1,%2,%3};"
        : "+f"(c[0]), "+f"(c[1]), "+f"(c[2]), "+f"(c[3])
        : "r"(a[0]), "r"(a[1]), "r"(a[2]), "r"(a[3]), "r"(b0), "r"(b1));
}

// S = Q K^T  (fully unrolled, ks-outer/nt-inner for accumulator ILP)
template<int NT>
__device__ __forceinline__ void s_phase(float (*sacc)[4], const uint32_t (*aqh)[4],
                                        const uint32_t (*aql)[4], uint32_t kaddr)
{
    #pragma unroll
    for (int ks = 0; ks < 4; ks++) {
        #pragma unroll
        for (int nt = 0; nt < NT; nt++) {
            uint32_t bb[4];
            ldsm4(bb, kaddr + (uint32_t)nt * 8 * ROWB + ks * 32);
            mma_bf16(sacc[nt], aqh[ks], bb[0], bb[1]);
            mma_bf16(sacc[nt], aqh[ks], bb[2], bb[3]);
            mma_bf16(sacc[nt], aql[ks], bb[0], bb[1]);
        }
    }
}

// masked exp + partial row sums
template<int NT>
__device__ __forceinline__ void exp_phase(float (*sacc)[4], int lkoff, int jbase,
                                          int m0, int cc, float& rs0, float& rs1)
{
    #pragma unroll
    for (int nt = 0; nt < NT; nt++) {
        int lk = lkoff + nt * 8 + cc;
        bool ok0a = ((unsigned)(lk     - m0) <= 2u * WIN) && ((unsigned)(jbase + lk)     < SEQ);
        bool ok0b = ((unsigned)(lk + 1 - m0) <= 2u * WIN) && ((unsigned)(jbase + lk + 1) < SEQ);
        bool ok1a = ((unsigned)(lk     - m0 - 8) <= 2u * WIN) && ((unsigned)(jbase + lk)     < SEQ);
        bool ok1b = ((unsigned)(lk + 1 - m0 - 8) <= 2u * WIN) && ((unsigned)(jbase + lk + 1) < SEQ);
        float p0 = ok0a ? ex2f(sacc[nt][0]) : 0.f;
        float p1 = ok0b ? ex2f(sacc[nt][1]) : 0.f;
        float p2 = ok1a ? ex2f(sacc[nt][2]) : 0.f;
        float p3 = ok1b ? ex2f(sacc[nt][3]) : 0.f;
        sacc[nt][0] = p0; sacc[nt][1] = p1; sacc[nt][2] = p2; sacc[nt][3] = p3;
        rs0 += p0 + p1;
        rs1 += p2 + p3;
    }
}

// O = P V  (fully unrolled; nt-inner gives independent oacc chains)
template<int NKS>
__device__ __forceinline__ void pv_phase(float (*oacc)[4], const float (*sacc)[4], uint32_t vaddr)
{
    #pragma unroll
    for (int ks = 0; ks < NKS; ks++) {
        uint32_t ah[4], al[4];
        split2(sacc[2*ks][0],   sacc[2*ks][1],   ah[0], al[0]);
        split2(sacc[2*ks][2],   sacc[2*ks][3],   ah[1], al[1]);
        split2(sacc[2*ks+1][0], sacc[2*ks+1][1], ah[2], al[2]);
        split2(sacc[2*ks+1][2], sacc[2*ks+1][3], ah[3], al[3]);
        #pragma unroll
        for (int nt = 0; nt < 8; nt++) {
            uint32_t bb[4];
            ldsm4t(bb, vaddr + (uint32_t)ks * 16 * ROWB + nt * 16);
            mma_bf16(oacc[nt], ah, bb[0], bb[1]);
            mma_bf16(oacc[nt], ah, bb[2], bb[3]);
            mma_bf16(oacc[nt], al, bb[0], bb[1]);
        }
    }
}

__global__ void __launch_bounds__(NTHREADS, 1)
swa_hmma_kernel(const float* __restrict__ q, const float* __restrict__ k,
                const float* __restrict__ v, float* __restrict__ out)
{
    extern __shared__ char smem[];
    const uint32_t sb = smem_u32(smem);
    const int t = threadIdx.x;

    const int tilesPerB = SEQ / QPB;
    const int b  = blockIdx.x / tilesPerB;
    const int Q0 = (blockIdx.x % tilesPerB) * QPB;

    const float* qb = q + (size_t)b * SEQ * DIM;
    const float* kb = k + (size_t)b * SEQ * DIM;
    const float* vb = v + (size_t)b * SEQ * DIM;
    float*       ob = out + (size_t)b * SEQ * DIM;

    // ---- stage K and V rows [Q0-64, Q0+192): two-pass for full MLP ----
    // strip-mined indices are affine in the iteration: c4 = t&15 (constant),
    // r_i = (t>>4) + 32*i. Pass 1: issue all 16 LDG.128 into registers.
    {
        const int c4 = t & 15;
        const int rb = t >> 4;
        float4 kbuf[8], vbuf[8];
        #pragma unroll
        for (int i = 0; i < 8; i++) {
            int j = Q0 - WIN + rb + 32 * i;
            bool ok = (j >= 0 && j < SEQ);
            const float4* kp = (const float4*)(kb + (size_t)j * DIM) + c4;
            const float4* vp = (const float4*)(vb + (size_t)j * DIM) + c4;
            kbuf[i] = ok ? __ldg(kp) : make_float4(0.f, 0.f, 0.f, 0.f);
            vbuf[i] = ok ? __ldg(vp) : make_float4(0.f, 0.f, 0.f, 0.f);
        }
        // Pass 2: convert + store (K first: V loads still landing)
        #pragma unroll
        for (int i = 0; i < 8; i++) {
            int r = rb + 32 * i;
            uint32_t h01, l01, h23, l23;
            split2(kbuf[i].x, kbuf[i].y, h01, l01);
            split2(kbuf[i].z, kbuf[i].w, h23, l23);
            *(uint2*)(smem + KH_OFF + r * ROWB + c4 * 8) = make_uint2(h01, h23);
            *(uint2*)(smem + KL_OFF + r * ROWB + c4 * 8) = make_uint2(l01, l23);
        }
        #pragma unroll
        for (int i = 0; i < 8; i++) {
            int r = rb + 32 * i;
            uint32_t h01, l01, h23, l23;
            split2(vbuf[i].x, vbuf[i].y, h01, l01);
            split2(vbuf[i].z, vbuf[i].w, h23, l23);
            *(uint2*)(smem + VH_OFF + r * ROWB + c4 * 8) = make_uint2(h01, h23);
            *(uint2*)(smem + VL_OFF + r * ROWB + c4 * 8) = make_uint2(l01, l23);
        }
    }

    const int w    = t >> 5;
    const int l    = t & 31;
    const int pair = w & 7;        // query group: rows Q0+pair*16 .. +15
    const int h    = w >> 3;       // key-span half: 0 -> lk [0,80), 1 -> lk [80,144)
    const int lkoff = h ? 80 : 0;

    // ---- build Q A-fragments straight from gmem (prescale + hi/lo split) ----
    // m16n8k16 A mapping: a0=(g, c2), a1=(g+8, c2), a2=(g, c2+8), a3=(g+8, c2+8)
    const float PRE = 0.125f * 1.4426950408889634f;   // 1/sqrt(D) * log2(e)
    uint32_t aqh[4][4], aql[4][4];
    {
        const int g  = l >> 2;
        const int c2 = (l & 3) * 2;
        const float* q0 = qb + (size_t)(Q0 + pair * 16 + g) * DIM + c2;
        const float* q1 = q0 + 8 * DIM;
        float2 f0[8], f1[8];
        #pragma unroll
        for (int ks = 0; ks < 4; ks++) {
            #pragma unroll
            for (int half = 0; half < 2; half++) {
                f0[ks * 2 + half] = *(const float2*)(q0 + ks * 16 + half * 8);
                f1[ks * 2 + half] = *(const float2*)(q1 + ks * 16 + half * 8);
            }
        }
        #pragma unroll
        for (int ks = 0; ks < 4; ks++) {
            #pragma unroll
            for (int half = 0; half < 2; half++) {
                float2 a0 = f0[ks * 2 + half], a1 = f1[ks * 2 + half];
                split2(a0.x * PRE, a0.y * PRE, aqh[ks][half * 2],     aql[ks][half * 2]);
                split2(a1.x * PRE, a1.y * PRE, aqh[ks][half * 2 + 1], aql[ks][half * 2 + 1]);
            }
        }
    }
    __syncthreads();

    // x4 lane addressing: lanes 0-15 -> KH col-chunks, lanes 16-31 -> KL
    const uint32_t kaddr = sb + KH_OFF
                         + (uint32_t)(pair * 16 + lkoff + (l & 7)) * ROWB
                         + ((l >> 3) & 1) * 16
                         + (l >> 4) * (KL_OFF - KH_OFF);
    // x4 trans lanes: 0-15 -> VH (16 rows), 16-31 -> VL
    const uint32_t vaddr = sb + VH_OFF
                         + (uint32_t)(pair * 16 + lkoff + (l & 7) + ((l >> 3) & 1) * 8) * ROWB
                         + (l >> 4) * (VL_OFF - VH_OFF);

    const int jbase = Q0 - WIN + pair * 16;
    const int m0 = l >> 2;
    const int cc = (l & 3) * 2;
    float rs0 = 0.f, rs1 = 0.f;

    float sacc[10][4];
    #pragma unroll
    for (int nt = 0; nt < 10; nt++)
        #pragma unroll
        for (int i = 0; i < 4; i++) sacc[nt][i] = 0.f;
    float oacc[8][4];
    #pragma unroll
    for (int nt = 0; nt < 8; nt++)
        #pragma unroll
        for (int i = 0; i < 4; i++) oacc[nt][i] = 0.f;

    if (h == 0) {
        s_phase<10>(sacc, aqh, aql, kaddr);
        exp_phase<10>(sacc, 0, jbase, m0, cc, rs0, rs1);
        pv_phase<5>(oacc, sacc, vaddr);
    } else {
        s_phase<8>(sacc, aqh, aql, kaddr);
        exp_phase<8>(sacc, 80, jbase, m0, cc, rs0, rs1);
        pv_phase<4>(oacc, sacc, vaddr);
    }

    rs0 += __shfl_xor_sync(0xFFFFFFFFu, rs0, 1);
    rs0 += __shfl_xor_sync(0xFFFFFFFFu, rs0, 2);
    rs1 += __shfl_xor_sync(0xFFFFFFFFu, rs1, 1);
    rs1 += __shfl_xor_sync(0xFFFFFFFFu, rs1, 2);

    // ---- combine halves via smem (reuse KH region, dead after S phase) ----
    float* cb = (float*)(smem + KH_OFF);
    __syncthreads();                               // all K/V tile reads done
    if (h == 1) {
        float* p0 = cb + (size_t)(pair * 16 + m0) * CBS;
        float* p1 = p0 + 8 * CBS;
        #pragma unroll
        for (int nt = 0; nt < 8; nt++) {
            *(float2*)(p0 + nt * 8 + cc) = make_float2(oacc[nt][0], oacc[nt][1]);
            *(float2*)(p1 + nt * 8 + cc) = make_float2(oacc[nt][2], oacc[nt][3]);
        }
        if (cc == 0) { p0[64] = rs0; p1[64] = rs1; }
    }
    __syncthreads();
    if (h == 0) {
        const float* p0 = cb + (size_t)(pair * 16 + m0) * CBS;
        const float* p1 = p0 + 8 * CBS;
        #pragma unroll
        for (int nt = 0; nt < 8; nt++) {
            float2 u0 = *(const float2*)(p0 + nt * 8 + cc);
            float2 u1 = *(const float2*)(p1 + nt * 8 + cc);
            oacc[nt][0] += u0.x; oacc[nt][1] += u0.y;
            oacc[nt][2] += u1.x; oacc[nt][3] += u1.y;
        }
        float inv0 = 1.f / (rs0 + p0[64]);
        float inv1 = 1.f / (rs1 + p1[64]);
        float* orow0 = ob + (size_t)(Q0 + pair * 16 + m0) * DIM;
        float* orow1 = orow0 + 8 * DIM;
        #pragma unroll
        for (int nt = 0; nt < 8; nt++) {
            *(float2*)(orow0 + nt * 8 + cc) = make_float2(oacc[nt][0] * inv0, oacc[nt][1] * inv0);
            *(float2*)(orow1 + nt * 8 + cc) = make_float2(oacc[nt][2] * inv1, oacc[nt][3] * inv1);
        }
    }
}

extern "C" void kernel_launch(void* const* d_in, const int* in_sizes, int n_in,
                              void* d_out, int out_size)
{
    const float* q = (const float*)d_in[0];
    const float* k = (const float*)d_in[1];
    const float* v = (const float*)d_in[2];
    float* out = (float*)d_out;

    int B = in_sizes[0] / (SEQ * DIM);

    cudaFuncSetAttribute(swa_hmma_kernel,
                         cudaFuncAttributeMaxDynamicSharedMemorySize, SMEM_BYTES);

    dim3 grid(B * (SEQ / QPB));
    swa_hmma_kernel<<<grid, NTHREADS, SMEM_BYTES>>>(q, k, v, out);
}

// round 12
// speedup vs baseline: 1.2202x; 1.0363x over previous
#include <cuda_runtime.h>
#include <cstdint>

#define SEQ 8192
#define DIM 64
#define WIN 64
#define QPB 128
#define NTHREADS 512
#define ROWS 256            // staged key rows: QPB + 2*WIN
#define ROWB 144            // smem row stride bytes: 64 halfs + 8 pad halfs

#define KH_OFF 0
#define VH_OFF (KH_OFF + ROWS*ROWB)
#define SMEM_BYTES (VH_OFF + ROWS*ROWB)   // 73728
#define CBS 68              // combine-buffer row stride in floats (272B)

__device__ __forceinline__ uint32_t smem_u32(const void* p) {
    uint32_t a; asm("{ .reg .u64 t; cvta.to.shared.u64 t, %1; cvt.u32.u64 %0, t; }" : "=r"(a) : "l"(p));
    return a;
}
__device__ __forceinline__ float ex2f(float x) { float r; asm("ex2.approx.f32 %0,%1;" : "=f"(r) : "f"(x)); return r; }

// pack {lo: a, hi: b} as f16x2 (round-to-nearest)
__device__ __forceinline__ uint32_t pack_f16x2(float a, float b) {
    uint32_t r; asm("cvt.rn.f16x2.f32 %0,%1,%2;" : "=r"(r) : "f"(b), "f"(a)); return r;
}
__device__ __forceinline__ void unpack_f16x2(uint32_t p, float& lo, float& hi) {
    asm("{ .reg .f16 l, h; mov.b32 {l, h}, %2; cvt.f32.f16 %0, l; cvt.f32.f16 %1, h; }"
        : "=f"(lo), "=f"(hi) : "r"(p));
}
// exact fp32 -> f16 hi + f16 residual split of a pair
__device__ __forceinline__ void split2h(float a, float b, uint32_t& h, uint32_t& l) {
    h = pack_f16x2(a, b);
    float fa, fb; unpack_f16x2(h, fa, fb);
    l = pack_f16x2(a - fa, b - fb);
}

__device__ __forceinline__ void ldsm4(uint32_t r[4], uint32_t addr) {
    asm volatile("ldmatrix.sync.aligned.m8n8.x4.shared.b16 {%0,%1,%2,%3}, [%4];"
        : "=r"(r[0]), "=r"(r[1]), "=r"(r[2]), "=r"(r[3]) : "r"(addr));
}
__device__ __forceinline__ void ldsm4t(uint32_t r[4], uint32_t addr) {
    asm volatile("ldmatrix.sync.aligned.m8n8.x4.trans.shared.b16 {%0,%1,%2,%3}, [%4];"
        : "=r"(r[0]), "=r"(r[1]), "=r"(r[2]), "=r"(r[3]) : "r"(addr));
}
__device__ __forceinline__ void mma_f16(float c[4], const uint32_t a[4], uint32_t b0, uint32_t b1) {
    asm volatile("mma.sync.aligned.m16n8k16.row.col.f32.f16.f16.f32 "
        "{%0,%1,%2,%3}, {%4,%5,%6,%7}, {%8,%9}, {%0,%1,%2,%3};"
        : "+f"(c[0]), "+f"(c[1]), "+f"(c[2]), "+f"(c[3])
        : "r"(a[0]), "r"(a[1]), "r"(a[2]), "r"(a[3]), "r"(b0), "r"(b1));
}

// S = (Qh + Ql) * Kh^T : per n-tile, two x4 ldmatrix fetch all 4 k-chunks
template<int NT>
__device__ __forceinline__ void s_phase(float (*sacc)[4], const uint32_t (*aqh)[4],
                                        const uint32_t (*aql)[4], uint32_t kaddr)
{
    #pragma unroll
    for (int nt = 0; nt < NT; nt++) {
        uint32_t b0[4], b1[4];
        ldsm4(b0, kaddr + (uint32_t)nt * 8 * ROWB);        // dims 0-31 (ks 0,1)
        ldsm4(b1, kaddr + (uint32_t)nt * 8 * ROWB + 64);   // dims 32-63 (ks 2,3)
        mma_f16(sacc[nt], aqh[0], b0[0], b0[1]);
        mma_f16(sacc[nt], aqh[1], b0[2], b0[3]);
        mma_f16(sacc[nt], aqh[2], b1[0], b1[1]);
        mma_f16(sacc[nt], aqh[3], b1[2], b1[3]);
        mma_f16(sacc[nt], aql[0], b0[0], b0[1]);
        mma_f16(sacc[nt], aql[1], b0[2], b0[3]);
        mma_f16(sacc[nt], aql[2], b1[0], b1[1]);
        mma_f16(sacc[nt], aql[3], b1[2], b1[3]);
    }
}

// masked exp + partial row sums
template<int NT>
__device__ __forceinline__ void exp_phase(float (*sacc)[4], int lkoff, int jbase,
                                          int m0, int cc, float& rs0, float& rs1)
{
    #pragma unroll
    for (int nt = 0; nt < NT; nt++) {
        int lk = lkoff + nt * 8 + cc;
        bool ok0a = ((unsigned)(lk     - m0) <= 2u * WIN) && ((unsigned)(jbase + lk)     < SEQ);
        bool ok0b = ((unsigned)(lk + 1 - m0) <= 2u * WIN) && ((unsigned)(jbase + lk + 1) < SEQ);
        bool ok1a = ((unsigned)(lk     - m0 - 8) <= 2u * WIN) && ((unsigned)(jbase + lk)     < SEQ);
        bool ok1b = ((unsigned)(lk + 1 - m0 - 8) <= 2u * WIN) && ((unsigned)(jbase + lk + 1) < SEQ);
        float p0 = ok0a ? ex2f(sacc[nt][0]) : 0.f;
        float p1 = ok0b ? ex2f(sacc[nt][1]) : 0.f;
        float p2 = ok1a ? ex2f(sacc[nt][2]) : 0.f;
        float p3 = ok1b ? ex2f(sacc[nt][3]) : 0.f;
        sacc[nt][0] = p0; sacc[nt][1] = p1; sacc[nt][2] = p2; sacc[nt][3] = p3;
        rs0 += p0 + p1;
        rs1 += p2 + p3;
    }
}

// O = (Ph + Pl) * Vh : x4 trans ldmatrix fetches two adjacent n-tiles
template<int NKS>
__device__ __forceinline__ void pv_phase(float (*oacc)[4], const float (*sacc)[4], uint32_t vaddr)
{
    #pragma unroll
    for (int ks = 0; ks < NKS; ks++) {
        uint32_t ah[4], al[4];
        split2h(sacc[2*ks][0],   sacc[2*ks][1],   ah[0], al[0]);
        split2h(sacc[2*ks][2],   sacc[2*ks][3],   ah[1], al[1]);
        split2h(sacc[2*ks+1][0], sacc[2*ks+1][1], ah[2], al[2]);
        split2h(sacc[2*ks+1][2], sacc[2*ks+1][3], ah[3], al[3]);
        #pragma unroll
        for (int nt0 = 0; nt0 < 8; nt0 += 2) {
            uint32_t bb[4];
            ldsm4t(bb, vaddr + (uint32_t)ks * 16 * ROWB + nt0 * 16);
            mma_f16(oacc[nt0],     ah, bb[0], bb[1]);
            mma_f16(oacc[nt0 + 1], ah, bb[2], bb[3]);
            mma_f16(oacc[nt0],     al, bb[0], bb[1]);
            mma_f16(oacc[nt0 + 1], al, bb[2], bb[3]);
        }
    }
}

__global__ void __launch_bounds__(NTHREADS, 1)
swa_hmma_kernel(const float* __restrict__ q, const float* __restrict__ k,
                const float* __restrict__ v, float* __restrict__ out)
{
    extern __shared__ char smem[];
    const uint32_t sb = smem_u32(smem);
    const int t = threadIdx.x;

    const int tilesPerB = SEQ / QPB;
    const int b  = blockIdx.x / tilesPerB;
    const int Q0 = (blockIdx.x % tilesPerB) * QPB;

    const float* qb = q + (size_t)b * SEQ * DIM;
    const float* kb = k + (size_t)b * SEQ * DIM;
    const float* vb = v + (size_t)b * SEQ * DIM;
    float*       ob = out + (size_t)b * SEQ * DIM;

    // ---- stage K/V rows [Q0-64, Q0+192): batched loads, then f16 convert ----
    {
        const int c4 = t & 15;
        const int rb = t >> 4;
        float4 kbuf[8], vbuf[8];
        #pragma unroll
        for (int i = 0; i < 8; i++) {
            int j = Q0 - WIN + rb + 32 * i;
            bool ok = (j >= 0 && j < SEQ);
            const float4* kp = (const float4*)(kb + (size_t)j * DIM) + c4;
            const float4* vp = (const float4*)(vb + (size_t)j * DIM) + c4;
            kbuf[i] = ok ? __ldg(kp) : make_float4(0.f, 0.f, 0.f, 0.f);
            vbuf[i] = ok ? __ldg(vp) : make_float4(0.f, 0.f, 0.f, 0.f);
        }
        #pragma unroll
        for (int i = 0; i < 8; i++) {
            int r = rb + 32 * i;
            *(uint2*)(smem + KH_OFF + r * ROWB + c4 * 8) =
                make_uint2(pack_f16x2(kbuf[i].x, kbuf[i].y), pack_f16x2(kbuf[i].z, kbuf[i].w));
        }
        #pragma unroll
        for (int i = 0; i < 8; i++) {
            int r = rb + 32 * i;
            *(uint2*)(smem + VH_OFF + r * ROWB + c4 * 8) =
                make_uint2(pack_f16x2(vbuf[i].x, vbuf[i].y), pack_f16x2(vbuf[i].z, vbuf[i].w));
        }
    }

    const int w    = t >> 5;
    const int l    = t & 31;
    const int pair = w & 7;        // query group: rows Q0+pair*16 .. +15
    const int h    = w >> 3;       // key-span half: 0 -> lk [0,80), 1 -> lk [80,144)
    const int lkoff = h ? 80 : 0;

    // ---- build Q A-fragments from gmem (prescale + exact f16 hi/lo split) ----
    // m16n8k16 A mapping: a0=(g, c2), a1=(g+8, c2), a2=(g, c2+8), a3=(g+8, c2+8)
    const float PRE = 0.125f * 1.4426950408889634f;   // 1/sqrt(D) * log2(e)
    uint32_t aqh[4][4], aql[4][4];
    {
        const int g  = l >> 2;
        const int c2 = (l & 3) * 2;
        const float* q0 = qb + (size_t)(Q0 + pair * 16 + g) * DIM + c2;
        const float* q1 = q0 + 8 * DIM;
        float2 f0[8], f1[8];
        #pragma unroll
        for (int ks = 0; ks < 4; ks++) {
            #pragma unroll
            for (int half = 0; half < 2; half++) {
                f0[ks * 2 + half] = *(const float2*)(q0 + ks * 16 + half * 8);
                f1[ks * 2 + half] = *(const float2*)(q1 + ks * 16 + half * 8);
            }
        }
        #pragma unroll
        for (int ks = 0; ks < 4; ks++) {
            #pragma unroll
            for (int half = 0; half < 2; half++) {
                float2 a0 = f0[ks * 2 + half], a1 = f1[ks * 2 + half];
                split2h(a0.x * PRE, a0.y * PRE, aqh[ks][half * 2],     aql[ks][half * 2]);
                split2h(a1.x * PRE, a1.y * PRE, aqh[ks][half * 2 + 1], aql[ks][half * 2 + 1]);
            }
        }
    }
    __syncthreads();

    // S-phase lane addressing: lane groups 0-7/8-15/16-23/24-31 -> col chunks 0/16/32/48
    const uint32_t kaddr = sb + KH_OFF
                         + (uint32_t)(pair * 16 + lkoff + (l & 7)) * ROWB
                         + (l >> 3) * 16;
    // PV x4t lanes: g0 rows 0-7 col+0, g1 rows 8-15 col+0, g2 rows 0-7 col+16, g3 rows 8-15 col+16
    const uint32_t vaddr = sb + VH_OFF
                         + (uint32_t)(pair * 16 + lkoff + (l & 7) + ((l >> 3) & 1) * 8) * ROWB
                         + (l >> 4) * 16;

    const int jbase = Q0 - WIN + pair * 16;
    const int m0 = l >> 2;
    const int cc = (l & 3) * 2;
    float rs0 = 0.f, rs1 = 0.f;

    float sacc[10][4];
    #pragma unroll
    for (int nt = 0; nt < 10; nt++)
        #pragma unroll
        for (int i = 0; i < 4; i++) sacc[nt][i] = 0.f;
    float oacc[8][4];
    #pragma unroll
    for (int nt = 0; nt < 8; nt++)
        #pragma unroll
        for (int i = 0; i < 4; i++) oacc[nt][i] = 0.f;

    if (h == 0) {
        s_phase<10>(sacc, aqh, aql, kaddr);
        exp_phase<10>(sacc, 0, jbase, m0, cc, rs0, rs1);
        pv_phase<5>(oacc, sacc, vaddr);
    } else {
        s_phase<8>(sacc, aqh, aql, kaddr);
        exp_phase<8>(sacc, 80, jbase, m0, cc, rs0, rs1);
        pv_phase<4>(oacc, sacc, vaddr);
    }

    rs0 += __shfl_xor_sync(0xFFFFFFFFu, rs0, 1);
    rs0 += __shfl_xor_sync(0xFFFFFFFFu, rs0, 2);
    rs1 += __shfl_xor_sync(0xFFFFFFFFu, rs1, 1);
    rs1 += __shfl_xor_sync(0xFFFFFFFFu, rs1, 2);

    // ---- combine halves via smem (reuse KH region, dead after S phase) ----
    float* cb = (float*)(smem + KH_OFF);
    __syncthreads();                               // all K tile reads done
    if (h == 1) {
        float* p0 = cb + (size_t)(pair * 16 + m0) * CBS;
        float* p1 = p0 + 8 * CBS;
        #pragma unroll
        for (int nt = 0; nt < 8; nt++) {
            *(float2*)(p0 + nt * 8 + cc) = make_float2(oacc[nt][0], oacc[nt][1]);
            *(float2*)(p1 + nt * 8 + cc) = make_float2(oacc[nt][2], oacc[nt][3]);
        }
        if (cc == 0) { p0[64] = rs0; p1[64] = rs1; }
    }
    __syncthreads();
    if (h == 0) {
        const float* p0 = cb + (size_t)(pair * 16 + m0) * CBS;
        const float* p1 = p0 + 8 * CBS;
        #pragma unroll
        for (int nt = 0; nt < 8; nt++) {
            float2 u0 = *(const float2*)(p0 + nt * 8 + cc);
            float2 u1 = *(const float2*)(p1 + nt * 8 + cc);
            oacc[nt][0] += u0.x; oacc[nt][1] += u0.y;
            oacc[nt][2] += u1.x; oacc[nt][3] += u1.y;
        }
        float inv0 = 1.f / (rs0 + p0[64]);
        float inv1 = 1.f / (rs1 + p1[64]);
        float* orow0 = ob + (size_t)(Q0 + pair * 16 + m0) * DIM;
        float* orow1 = orow0 + 8 * DIM;
        #pragma unroll
        for (int nt = 0; nt < 8; nt++) {
            *(float2*)(orow0 + nt * 8 + cc) = make_float2(oacc[nt][0] * inv0, oacc[nt][1] * inv0);
            *(float2*)(orow1 + nt * 8 + cc) = make_float2(oacc[nt][2] * inv1, oacc[nt][3] * inv1);
        }
    }
}

extern "C" void kernel_launch(void* const* d_in, const int* in_sizes, int n_in,
                              void* d_out, int out_size)
{
    const float* q = (const float*)d_in[0];
    const float* k = (const float*)d_in[1];
    const float* v = (const float*)d_in[2];
    float* out = (float*)d_out;

    int B = in_sizes[0] / (SEQ * DIM);

    cudaFuncSetAttribute(swa_hmma_kernel,
                         cudaFuncAttributeMaxDynamicSharedMemorySize, SMEM_BYTES);

    dim3 grid(B * (SEQ / QPB));
    swa_hmma_kernel<<<grid, NTHREADS, SMEM_BYTES>>>(q, k, v, out);
}

// round 13
// speedup vs baseline: 1.4018x; 1.1488x over previous
#include <cuda_runtime.h>
#include <cstdint>

#define SEQ 8192
#define DIM 64
#define WIN 64
#define QPB 128
#define NTHREADS 512
#define ROWS 256            // staged key rows: QPB + 2*WIN
#define ROWB 144            // smem row stride bytes: 64 halfs + 8 pad halfs

#define KH_OFF 0
#define VH_OFF (KH_OFF + ROWS*ROWB)
#define CB_OFF (VH_OFF + ROWS*ROWB)       // dedicated combine buffer
#define CBS 68                            // combine row stride in floats (272B)
#define SMEM_BYTES (CB_OFF + QPB*CBS*4)   // 73728 + 34816 = 108544

__device__ __forceinline__ uint32_t smem_u32(const void* p) {
    uint32_t a; asm("{ .reg .u64 t; cvta.to.shared.u64 t, %1; cvt.u32.u64 %0, t; }" : "=r"(a) : "l"(p));
    return a;
}
__device__ __forceinline__ float ex2f(float x) { float r; asm("ex2.approx.f32 %0,%1;" : "=f"(r) : "f"(x)); return r; }

// pack {lo: a, hi: b} as f16x2 (round-to-nearest)
__device__ __forceinline__ uint32_t pack_f16x2(float a, float b) {
    uint32_t r; asm("cvt.rn.f16x2.f32 %0,%1,%2;" : "=r"(r) : "f"(b), "f"(a)); return r;
}

__device__ __forceinline__ void ldsm4(uint32_t r[4], uint32_t addr) {
    asm volatile("ldmatrix.sync.aligned.m8n8.x4.shared.b16 {%0,%1,%2,%3}, [%4];"
        : "=r"(r[0]), "=r"(r[1]), "=r"(r[2]), "=r"(r[3]) : "r"(addr));
}
__device__ __forceinline__ void ldsm4t(uint32_t r[4], uint32_t addr) {
    asm volatile("ldmatrix.sync.aligned.m8n8.x4.trans.shared.b16 {%0,%1,%2,%3}, [%4];"
        : "=r"(r[0]), "=r"(r[1]), "=r"(r[2]), "=r"(r[3]) : "r"(addr));
}
__device__ __forceinline__ void mma_f16(float c[4], const uint32_t a[4], uint32_t b0, uint32_t b1) {
    asm volatile("mma.sync.aligned.m16n8k16.row.col.f32.f16.f16.f32 "
        "{%0,%1,%2,%3}, {%4,%5,%6,%7}, {%8,%9}, {%0,%1,%2,%3};"
        : "+f"(c[0]), "+f"(c[1]), "+f"(c[2]), "+f"(c[3])
        : "r"(a[0]), "r"(a[1]), "r"(a[2]), "r"(a[3]), "r"(b0), "r"(b1));
}
#define BAR_PAIR(id) asm volatile("bar.sync %0, 64;" :: "r"(id) : "memory")

// S = Qh * Kh^T : per n-tile, two x4 ldmatrix fetch all 4 k-chunks
template<int NT>
__device__ __forceinline__ void s_phase(float (*sacc)[4], const uint32_t (*aqh)[4], uint32_t kaddr)
{
    #pragma unroll
    for (int nt = 0; nt < NT; nt++) {
        uint32_t b0[4], b1[4];
        ldsm4(b0, kaddr + (uint32_t)nt * 8 * ROWB);        // dims 0-31 (ks 0,1)
        ldsm4(b1, kaddr + (uint32_t)nt * 8 * ROWB + 64);   // dims 32-63 (ks 2,3)
        mma_f16(sacc[nt], aqh[0], b0[0], b0[1]);
        mma_f16(sacc[nt], aqh[1], b0[2], b0[3]);
        mma_f16(sacc[nt], aqh[2], b1[0], b1[1]);
        mma_f16(sacc[nt], aqh[3], b1[2], b1[3]);
    }
}

// masked exp + partial row sums
template<int NT>
__device__ __forceinline__ void exp_phase(float (*sacc)[4], int lkoff, int jbase,
                                          int m0, int cc, float& rs0, float& rs1)
{
    #pragma unroll
    for (int nt = 0; nt < NT; nt++) {
        int lk = lkoff + nt * 8 + cc;
        bool ok0a = ((unsigned)(lk     - m0) <= 2u * WIN) && ((unsigned)(jbase + lk)     < SEQ);
        bool ok0b = ((unsigned)(lk + 1 - m0) <= 2u * WIN) && ((unsigned)(jbase + lk + 1) < SEQ);
        bool ok1a = ((unsigned)(lk     - m0 - 8) <= 2u * WIN) && ((unsigned)(jbase + lk)     < SEQ);
        bool ok1b = ((unsigned)(lk + 1 - m0 - 8) <= 2u * WIN) && ((unsigned)(jbase + lk + 1) < SEQ);
        float p0 = ok0a ? ex2f(sacc[nt][0]) : 0.f;
        float p1 = ok0b ? ex2f(sacc[nt][1]) : 0.f;
        float p2 = ok1a ? ex2f(sacc[nt][2]) : 0.f;
        float p3 = ok1b ? ex2f(sacc[nt][3]) : 0.f;
        sacc[nt][0] = p0; sacc[nt][1] = p1; sacc[nt][2] = p2; sacc[nt][3] = p3;
        rs0 += p0 + p1;
        rs1 += p2 + p3;
    }
}

// O = Ph * Vh : x4 trans ldmatrix fetches two adjacent n-tiles
template<int NKS>
__device__ __forceinline__ void pv_phase(float (*oacc)[4], const float (*sacc)[4], uint32_t vaddr)
{
    #pragma unroll
    for (int ks = 0; ks < NKS; ks++) {
        uint32_t ah[4];
        ah[0] = pack_f16x2(sacc[2*ks][0],   sacc[2*ks][1]);
        ah[1] = pack_f16x2(sacc[2*ks][2],   sacc[2*ks][3]);
        ah[2] = pack_f16x2(sacc[2*ks+1][0], sacc[2*ks+1][1]);
        ah[3] = pack_f16x2(sacc[2*ks+1][2], sacc[2*ks+1][3]);
        #pragma unroll
        for (int nt0 = 0; nt0 < 8; nt0 += 2) {
            uint32_t bb[4];
            ldsm4t(bb, vaddr + (uint32_t)ks * 16 * ROWB + nt0 * 16);
            mma_f16(oacc[nt0],     ah, bb[0], bb[1]);
            mma_f16(oacc[nt0 + 1], ah, bb[2], bb[3]);
        }
    }
}

__global__ void __launch_bounds__(NTHREADS, 1)
swa_hmma_kernel(const float* __restrict__ q, const float* __restrict__ k,
                const float* __restrict__ v, float* __restrict__ out)
{
    extern __shared__ char smem[];
    const uint32_t sb = smem_u32(smem);
    const int t = threadIdx.x;

    const int tilesPerB = SEQ / QPB;
    const int b  = blockIdx.x / tilesPerB;
    const int Q0 = (blockIdx.x % tilesPerB) * QPB;

    const float* qb = q + (size_t)b * SEQ * DIM;
    const float* kb = k + (size_t)b * SEQ * DIM;
    const float* vb = v + (size_t)b * SEQ * DIM;
    float*       ob = out + (size_t)b * SEQ * DIM;

    // ---- stage K/V rows [Q0-64, Q0+192): batched loads, then f16 convert ----
    {
        const int c4 = t & 15;
        const int rb = t >> 4;
        float4 kbuf[8], vbuf[8];
        #pragma unroll
        for (int i = 0; i < 8; i++) {
            int j = Q0 - WIN + rb + 32 * i;
            bool ok = (j >= 0 && j < SEQ);
            const float4* kp = (const float4*)(kb + (size_t)j * DIM) + c4;
            const float4* vp = (const float4*)(vb + (size_t)j * DIM) + c4;
            kbuf[i] = ok ? __ldg(kp) : make_float4(0.f, 0.f, 0.f, 0.f);
            vbuf[i] = ok ? __ldg(vp) : make_float4(0.f, 0.f, 0.f, 0.f);
        }
        #pragma unroll
        for (int i = 0; i < 8; i++) {
            int r = rb + 32 * i;
            *(uint2*)(smem + KH_OFF + r * ROWB + c4 * 8) =
                make_uint2(pack_f16x2(kbuf[i].x, kbuf[i].y), pack_f16x2(kbuf[i].z, kbuf[i].w));
        }
        #pragma unroll
        for (int i = 0; i < 8; i++) {
            int r = rb + 32 * i;
            *(uint2*)(smem + VH_OFF + r * ROWB + c4 * 8) =
                make_uint2(pack_f16x2(vbuf[i].x, vbuf[i].y), pack_f16x2(vbuf[i].z, vbuf[i].w));
        }
    }

    const int w    = t >> 5;
    const int l    = t & 31;
    const int pair = w & 7;        // query group: rows Q0+pair*16 .. +15
    const int h    = w >> 3;       // key-span half: 0 -> lk [0,80), 1 -> lk [80,144)
    const int lkoff = h ? 80 : 0;

    // ---- build Q A-fragments from gmem (prescale + single f16 convert) ----
    // m16n8k16 A mapping: a0=(g, c2), a1=(g+8, c2), a2=(g, c2+8), a3=(g+8, c2+8)
    const float PRE = 0.125f * 1.4426950408889634f;   // 1/sqrt(D) * log2(e)
    uint32_t aqh[4][4];
    {
        const int g  = l >> 2;
        const int c2 = (l & 3) * 2;
        const float* q0 = qb + (size_t)(Q0 + pair * 16 + g) * DIM + c2;
        const float* q1 = q0 + 8 * DIM;
        float2 f0[8], f1[8];
        #pragma unroll
        for (int ks = 0; ks < 4; ks++) {
            #pragma unroll
            for (int half = 0; half < 2; half++) {
                f0[ks * 2 + half] = *(const float2*)(q0 + ks * 16 + half * 8);
                f1[ks * 2 + half] = *(const float2*)(q1 + ks * 16 + half * 8);
            }
        }
        #pragma unroll
        for (int ks = 0; ks < 4; ks++) {
            #pragma unroll
            for (int half = 0; half < 2; half++) {
                float2 a0 = f0[ks * 2 + half], a1 = f1[ks * 2 + half];
                aqh[ks][half * 2]     = pack_f16x2(a0.x * PRE, a0.y * PRE);
                aqh[ks][half * 2 + 1] = pack_f16x2(a1.x * PRE, a1.y * PRE);
            }
        }
    }
    __syncthreads();

    // S-phase lane addressing: lane groups 0-7/8-15/16-23/24-31 -> col chunks 0/16/32/48
    const uint32_t kaddr = sb + KH_OFF
                         + (uint32_t)(pair * 16 + lkoff + (l & 7)) * ROWB
                         + (l >> 3) * 16;
    // PV x4t lanes: g0 rows 0-7 col+0, g1 rows 8-15 col+0, g2 rows 0-7 col+16, g3 rows 8-15 col+16
    const uint32_t vaddr = sb + VH_OFF
                         + (uint32_t)(pair * 16 + lkoff + (l & 7) + ((l >> 3) & 1) * 8) * ROWB
                         + (l >> 4) * 16;

    const int jbase = Q0 - WIN + pair * 16;
    const int m0 = l >> 2;
    const int cc = (l & 3) * 2;
    float rs0 = 0.f, rs1 = 0.f;

    float sacc[10][4];
    #pragma unroll
    for (int nt = 0; nt < 10; nt++)
        #pragma unroll
        for (int i = 0; i < 4; i++) sacc[nt][i] = 0.f;
    float oacc[8][4];
    #pragma unroll
    for (int nt = 0; nt < 8; nt++)
        #pragma unroll
        for (int i = 0; i < 4; i++) oacc[nt][i] = 0.f;

    if (h == 0) {
        s_phase<10>(sacc, aqh, kaddr);
        exp_phase<10>(sacc, 0, jbase, m0, cc, rs0, rs1);
        pv_phase<5>(oacc, sacc, vaddr);
    } else {
        s_phase<8>(sacc, aqh, kaddr);
        exp_phase<8>(sacc, 80, jbase, m0, cc, rs0, rs1);
        pv_phase<4>(oacc, sacc, vaddr);
    }

    rs0 += __shfl_xor_sync(0xFFFFFFFFu, rs0, 1);
    rs0 += __shfl_xor_sync(0xFFFFFFFFu, rs0, 2);
    rs1 += __shfl_xor_sync(0xFFFFFFFFu, rs1, 1);
    rs1 += __shfl_xor_sync(0xFFFFFFFFu, rs1, 2);

    // ---- combine halves via dedicated smem buffer, per-pair named barrier ----
    float* cb = (float*)(smem + CB_OFF);
    if (h == 1) {
        float* p0 = cb + (size_t)(pair * 16 + m0) * CBS;
        float* p1 = p0 + 8 * CBS;
        #pragma unroll
        for (int nt = 0; nt < 8; nt++) {
            *(float2*)(p0 + nt * 8 + cc) = make_float2(oacc[nt][0], oacc[nt][1]);
            *(float2*)(p1 + nt * 8 + cc) = make_float2(oacc[nt][2], oacc[nt][3]);
        }
        if (cc == 0) { p0[64] = rs0; p1[64] = rs1; }
    }
    BAR_PAIR(pair + 1);            // syncs only the 2 warps of this pair
    if (h == 0) {
        const float* p0 = cb + (size_t)(pair * 16 + m0) * CBS;
        const float* p1 = p0 + 8 * CBS;
        #pragma unroll
        for (int nt = 0; nt < 8; nt++) {
            float2 u0 = *(const float2*)(p0 + nt * 8 + cc);
            float2 u1 = *(const float2*)(p1 + nt * 8 + cc);
            oacc[nt][0] += u0.x; oacc[nt][1] += u0.y;
            oacc[nt][2] += u1.x; oacc[nt][3] += u1.y;
        }
        float inv0 = 1.f / (rs0 + p0[64]);
        float inv1 = 1.f / (rs1 + p1[64]);
        float* orow0 = ob + (size_t)(Q0 + pair * 16 + m0) * DIM;
        float* orow1 = orow0 + 8 * DIM;
        #pragma unroll
        for (int nt = 0; nt < 8; nt++) {
            *(float2*)(orow0 + nt * 8 + cc) = make_float2(oacc[nt][0] * inv0, oacc[nt][1] * inv0);
            *(float2*)(orow1 + nt * 8 + cc) = make_float2(oacc[nt][2] * inv1, oacc[nt][3] * inv1);
        }
    }
}

extern "C" void kernel_launch(void* const* d_in, const int* in_sizes, int n_in,
                              void* d_out, int out_size)
{
    const float* q = (const float*)d_in[0];
    const float* k = (const float*)d_in[1];
    const float* v = (const float*)d_in[2];
    float* out = (float*)d_out;

    int B = in_sizes[0] / (SEQ * DIM);

    cudaFuncSetAttribute(swa_hmma_kernel,
                         cudaFuncAttributeMaxDynamicSharedMemorySize, SMEM_BYTES);

    dim3 grid(B * (SEQ / QPB));
    swa_hmma_kernel<<<grid, NTHREADS, SMEM_BYTES>>>(q, k, v, out);
}

// round 14
// speedup vs baseline: 1.4060x; 1.0030x over previous
#include <cuda_runtime.h>
#include <cstdint>

#define SEQ 8192
#define DIM 64
#define WIN 64
#define QPB 64
#define NTHREADS 256
#define ROWS 192            // staged key rows: QPB + 2*WIN
#define ROWB 144            // smem row stride bytes: 64 halfs + 8 pad halfs

#define KH_OFF 0
#define VH_OFF (KH_OFF + ROWS*ROWB)
#define CB_OFF (VH_OFF + ROWS*ROWB)       // dedicated combine buffer
#define CBS 68                            // combine row stride in floats (272B)
#define SMEM_BYTES (CB_OFF + QPB*CBS*4)   // 55296 + 17408 = 72704

__device__ __forceinline__ uint32_t smem_u32(const void* p) {
    uint32_t a; asm("{ .reg .u64 t; cvta.to.shared.u64 t, %1; cvt.u32.u64 %0, t; }" : "=r"(a) : "l"(p));
    return a;
}
__device__ __forceinline__ float ex2f(float x) { float r; asm("ex2.approx.f32 %0,%1;" : "=f"(r) : "f"(x)); return r; }

// pack {lo: a, hi: b} as f16x2 (round-to-nearest)
__device__ __forceinline__ uint32_t pack_f16x2(float a, float b) {
    uint32_t r; asm("cvt.rn.f16x2.f32 %0,%1,%2;" : "=r"(r) : "f"(b), "f"(a)); return r;
}

__device__ __forceinline__ void ldsm4(uint32_t r[4], uint32_t addr) {
    asm volatile("ldmatrix.sync.aligned.m8n8.x4.shared.b16 {%0,%1,%2,%3}, [%4];"
        : "=r"(r[0]), "=r"(r[1]), "=r"(r[2]), "=r"(r[3]) : "r"(addr));
}
__device__ __forceinline__ void ldsm4t(uint32_t r[4], uint32_t addr) {
    asm volatile("ldmatrix.sync.aligned.m8n8.x4.trans.shared.b16 {%0,%1,%2,%3}, [%4];"
        : "=r"(r[0]), "=r"(r[1]), "=r"(r[2]), "=r"(r[3]) : "r"(addr));
}
__device__ __forceinline__ void mma_f16(float c[4], const uint32_t a[4], uint32_t b0, uint32_t b1) {
    asm volatile("mma.sync.aligned.m16n8k16.row.col.f32.f16.f16.f32 "
        "{%0,%1,%2,%3}, {%4,%5,%6,%7}, {%8,%9}, {%0,%1,%2,%3};"
        : "+f"(c[0]), "+f"(c[1]), "+f"(c[2]), "+f"(c[3])
        : "r"(a[0]), "r"(a[1]), "r"(a[2]), "r"(a[3]), "r"(b0), "r"(b1));
}
#define BAR_PAIR(id) asm volatile("bar.sync %0, 64;" :: "r"(id) : "memory")

// S = Qh * Kh^T : per n-tile, two x4 ldmatrix fetch all 4 k-chunks
template<int NT>
__device__ __forceinline__ void s_phase(float (*sacc)[4], const uint32_t (*aqh)[4], uint32_t kaddr)
{
    #pragma unroll
    for (int nt = 0; nt < NT; nt++) {
        uint32_t b0[4], b1[4];
        ldsm4(b0, kaddr + (uint32_t)nt * 8 * ROWB);        // dims 0-31 (ks 0,1)
        ldsm4(b1, kaddr + (uint32_t)nt * 8 * ROWB + 64);   // dims 32-63 (ks 2,3)
        mma_f16(sacc[nt], aqh[0], b0[0], b0[1]);
        mma_f16(sacc[nt], aqh[1], b0[2], b0[3]);
        mma_f16(sacc[nt], aqh[2], b1[0], b1[1]);
        mma_f16(sacc[nt], aqh[3], b1[2], b1[3]);
    }
}

// masked exp + partial row sums
template<int NT>
__device__ __forceinline__ void exp_phase(float (*sacc)[4], int lkoff, int jbase,
                                          int m0, int cc, float& rs0, float& rs1)
{
    #pragma unroll
    for (int nt = 0; nt < NT; nt++) {
        int lk = lkoff + nt * 8 + cc;
        bool ok0a = ((unsigned)(lk     - m0) <= 2u * WIN) && ((unsigned)(jbase + lk)     < SEQ);
        bool ok0b = ((unsigned)(lk + 1 - m0) <= 2u * WIN) && ((unsigned)(jbase + lk + 1) < SEQ);
        bool ok1a = ((unsigned)(lk     - m0 - 8) <= 2u * WIN) && ((unsigned)(jbase + lk)     < SEQ);
        bool ok1b = ((unsigned)(lk + 1 - m0 - 8) <= 2u * WIN) && ((unsigned)(jbase + lk + 1) < SEQ);
        float p0 = ok0a ? ex2f(sacc[nt][0]) : 0.f;
        float p1 = ok0b ? ex2f(sacc[nt][1]) : 0.f;
        float p2 = ok1a ? ex2f(sacc[nt][2]) : 0.f;
        float p3 = ok1b ? ex2f(sacc[nt][3]) : 0.f;
        sacc[nt][0] = p0; sacc[nt][1] = p1; sacc[nt][2] = p2; sacc[nt][3] = p3;
        rs0 += p0 + p1;
        rs1 += p2 + p3;
    }
}

// O = Ph * Vh : x4 trans ldmatrix fetches two adjacent n-tiles
template<int NKS>
__device__ __forceinline__ void pv_phase(float (*oacc)[4], const float (*sacc)[4], uint32_t vaddr)
{
    #pragma unroll
    for (int ks = 0; ks < NKS; ks++) {
        uint32_t ah[4];
        ah[0] = pack_f16x2(sacc[2*ks][0],   sacc[2*ks][1]);
        ah[1] = pack_f16x2(sacc[2*ks][2],   sacc[2*ks][3]);
        ah[2] = pack_f16x2(sacc[2*ks+1][0], sacc[2*ks+1][1]);
        ah[3] = pack_f16x2(sacc[2*ks+1][2], sacc[2*ks+1][3]);
        #pragma unroll
        for (int nt0 = 0; nt0 < 8; nt0 += 2) {
            uint32_t bb[4];
            ldsm4t(bb, vaddr + (uint32_t)ks * 16 * ROWB + nt0 * 16);
            mma_f16(oacc[nt0],     ah, bb[0], bb[1]);
            mma_f16(oacc[nt0 + 1], ah, bb[2], bb[3]);
        }
    }
}

__global__ void __launch_bounds__(NTHREADS, 2)
swa_hmma_kernel(const float* __restrict__ q, const float* __restrict__ k,
                const float* __restrict__ v, float* __restrict__ out)
{
    extern __shared__ char smem[];
    const uint32_t sb = smem_u32(smem);
    const int t = threadIdx.x;

    const int tilesPerB = SEQ / QPB;
    const int b  = blockIdx.x / tilesPerB;
    const int Q0 = (blockIdx.x % tilesPerB) * QPB;

    const float* qb = q + (size_t)b * SEQ * DIM;
    const float* kb = k + (size_t)b * SEQ * DIM;
    const float* vb = v + (size_t)b * SEQ * DIM;
    float*       ob = out + (size_t)b * SEQ * DIM;

    // ---- stage K/V rows [Q0-64, Q0+128): batched loads, then f16 convert ----
    {
        const int c4 = t & 15;
        const int rb = t >> 4;
        float4 kbuf[12], vbuf[12];
        #pragma unroll
        for (int i = 0; i < 12; i++) {
            int j = Q0 - WIN + rb + 16 * i;
            bool ok = (j >= 0 && j < SEQ);
            const float4* kp = (const float4*)(kb + (size_t)j * DIM) + c4;
            const float4* vp = (const float4*)(vb + (size_t)j * DIM) + c4;
            kbuf[i] = ok ? __ldg(kp) : make_float4(0.f, 0.f, 0.f, 0.f);
            vbuf[i] = ok ? __ldg(vp) : make_float4(0.f, 0.f, 0.f, 0.f);
        }
        #pragma unroll
        for (int i = 0; i < 12; i++) {
            int r = rb + 16 * i;
            *(uint2*)(smem + KH_OFF + r * ROWB + c4 * 8) =
                make_uint2(pack_f16x2(kbuf[i].x, kbuf[i].y), pack_f16x2(kbuf[i].z, kbuf[i].w));
        }
        #pragma unroll
        for (int i = 0; i < 12; i++) {
            int r = rb + 16 * i;
            *(uint2*)(smem + VH_OFF + r * ROWB + c4 * 8) =
                make_uint2(pack_f16x2(vbuf[i].x, vbuf[i].y), pack_f16x2(vbuf[i].z, vbuf[i].w));
        }
    }

    const int w    = t >> 5;
    const int l    = t & 31;
    const int pair = w & 3;        // query group: rows Q0+pair*16 .. +15
    const int h    = w >> 2;       // key-span half: 0 -> lk [0,80), 1 -> lk [80,144)
    const int lkoff = h ? 80 : 0;

    // ---- build Q A-fragments from gmem (prescale + single f16 convert) ----
    // m16n8k16 A mapping: a0=(g, c2), a1=(g+8, c2), a2=(g, c2+8), a3=(g+8, c2+8)
    const float PRE = 0.125f * 1.4426950408889634f;   // 1/sqrt(D) * log2(e)
    uint32_t aqh[4][4];
    {
        const int g  = l >> 2;
        const int c2 = (l & 3) * 2;
        const float* q0 = qb + (size_t)(Q0 + pair * 16 + g) * DIM + c2;
        const float* q1 = q0 + 8 * DIM;
        float2 f0[8], f1[8];
        #pragma unroll
        for (int ks = 0; ks < 4; ks++) {
            #pragma unroll
            for (int half = 0; half < 2; half++) {
                f0[ks * 2 + half] = *(const float2*)(q0 + ks * 16 + half * 8);
                f1[ks * 2 + half] = *(const float2*)(q1 + ks * 16 + half * 8);
            }
        }
        #pragma unroll
        for (int ks = 0; ks < 4; ks++) {
            #pragma unroll
            for (int half = 0; half < 2; half++) {
                float2 a0 = f0[ks * 2 + half], a1 = f1[ks * 2 + half];
                aqh[ks][half * 2]     = pack_f16x2(a0.x * PRE, a0.y * PRE);
                aqh[ks][half * 2 + 1] = pack_f16x2(a1.x * PRE, a1.y * PRE);
            }
        }
    }
    __syncthreads();

    // S-phase lane addressing: lane groups 0-7/8-15/16-23/24-31 -> col chunks 0/16/32/48
    const uint32_t kaddr = sb + KH_OFF
                         + (uint32_t)(pair * 16 + lkoff + (l & 7)) * ROWB
                         + (l >> 3) * 16;
    // PV x4t lanes: g0 rows 0-7 col+0, g1 rows 8-15 col+0, g2 rows 0-7 col+16, g3 rows 8-15 col+16
    const uint32_t vaddr = sb + VH_OFF
                         + (uint32_t)(pair * 16 + lkoff + (l & 7) + ((l >> 3) & 1) * 8) * ROWB
                         + (l >> 4) * 16;

    const int jbase = Q0 - WIN + pair * 16;
    const int m0 = l >> 2;
    const int cc = (l & 3) * 2;
    float rs0 = 0.f, rs1 = 0.f;

    float sacc[10][4];
    #pragma unroll
    for (int nt = 0; nt < 10; nt++)
        #pragma unroll
        for (int i = 0; i < 4; i++) sacc[nt][i] = 0.f;
    float oacc[8][4];
    #pragma unroll
    for (int nt = 0; nt < 8; nt++)
        #pragma unroll
        for (int i = 0; i < 4; i++) oacc[nt][i] = 0.f;

    if (h == 0) {
        s_phase<10>(sacc, aqh, kaddr);
        exp_phase<10>(sacc, 0, jbase, m0, cc, rs0, rs1);
        pv_phase<5>(oacc, sacc, vaddr);
    } else {
        s_phase<8>(sacc, aqh, kaddr);
        exp_phase<8>(sacc, 80, jbase, m0, cc, rs0, rs1);
        pv_phase<4>(oacc, sacc, vaddr);
    }

    rs0 += __shfl_xor_sync(0xFFFFFFFFu, rs0, 1);
    rs0 += __shfl_xor_sync(0xFFFFFFFFu, rs0, 2);
    rs1 += __shfl_xor_sync(0xFFFFFFFFu, rs1, 1);
    rs1 += __shfl_xor_sync(0xFFFFFFFFu, rs1, 2);

    // ---- combine halves via dedicated smem buffer, per-pair named barrier ----
    float* cb = (float*)(smem + CB_OFF);
    if (h == 1) {
        float* p0 = cb + (size_t)(pair * 16 + m0) * CBS;
        float* p1 = p0 + 8 * CBS;
        #pragma unroll
        for (int nt = 0; nt < 8; nt++) {
            *(float2*)(p0 + nt * 8 + cc) = make_float2(oacc[nt][0], oacc[nt][1]);
            *(float2*)(p1 + nt * 8 + cc) = make_float2(oacc[nt][2], oacc[nt][3]);
        }
        if (cc == 0) { p0[64] = rs0; p1[64] = rs1; }
    }
    BAR_PAIR(pair + 1);            // syncs only the 2 warps of this pair
    if (h == 0) {
        const float* p0 = cb + (size_t)(pair * 16 + m0) * CBS;
        const float* p1 = p0 + 8 * CBS;
        #pragma unroll
        for (int nt = 0; nt < 8; nt++) {
            float2 u0 = *(const float2*)(p0 + nt * 8 + cc);
            float2 u1 = *(const float2*)(p1 + nt * 8 + cc);
            oacc[nt][0] += u0.x; oacc[nt][1] += u0.y;
            oacc[nt][2] += u1.x; oacc[nt][3] += u1.y;
        }
        float inv0 = 1.f / (rs0 + p0[64]);
        float inv1 = 1.f / (rs1 + p1[64]);
        float* orow0 = ob + (size_t)(Q0 + pair * 16 + m0) * DIM;
        float* orow1 = orow0 + 8 * DIM;
        #pragma unroll
        for (int nt = 0; nt < 8; nt++) {
            *(float2*)(orow0 + nt * 8 + cc) = make_float2(oacc[nt][0] * inv0, oacc[nt][1] * inv0);
            *(float2*)(orow1 + nt * 8 + cc) = make_float2(oacc[nt][2] * inv1, oacc[nt][3] * inv1);
        }
    }
}

extern "C" void kernel_launch(void* const* d_in, const int* in_sizes, int n_in,
                              void* d_out, int out_size)
{
    const float* q = (const float*)d_in[0];
    const float* k = (const float*)d_in[1];
    const float* v = (const float*)d_in[2];
    float* out = (float*)d_out;

    int B = in_sizes[0] / (SEQ * DIM);

    cudaFuncSetAttribute(swa_hmma_kernel,
                         cudaFuncAttributeMaxDynamicSharedMemorySize, SMEM_BYTES);

    dim3 grid(B * (SEQ / QPB));
    swa_hmma_kernel<<<grid, NTHREADS, SMEM_BYTES>>>(q, k, v, out);
}